// round 13
// baseline (speedup 1.0000x reference)
#include <cuda_runtime.h>
#include <math.h>

#define HW 24
#define NPOS 576
#define XZQ 442368            // one K-quarter of xz: 2n * 384 * 576

// Scratch (__device__ globals: allocation-free rule)
__device__ float g_xz[4 * XZQ];          // [kq][n][384][576]
__device__ float g_mid[2 * 96 * NPOS];
__device__ float g_wT[2 * 864 * 384];
__device__ float g_rs0[2 * 96 * 24];     // layer-0 rms row scales
__device__ float g_rs1[2 * 96 * 24];     // layer-1 rms row scales
__device__ float4 g_xp2[2 * 48 * 38];    // x_proj interleaved [c4][j] float4
__device__ float4 g_op2[2 * 48 * 96];    // out_proj interleaved [c4][k] float4

typedef unsigned long long ull;

__device__ __forceinline__ void ffma2(ull& acc, ull a, ull b) {
    asm("fma.rn.f32x2 %0, %1, %2, %0;" : "+l"(acc) : "l"(a), "l"(b));
}
__device__ __forceinline__ float2 up(ull a) { return *(float2*)&a; }

// ---------- weight transpose (conv): [co][ci*9+t] -> [ci*9+t][co] ----------
__global__ void wt_kernel(const float* __restrict__ ipw) {
    __shared__ float tile[32][33];
    int r0 = blockIdx.x * 32, c0 = blockIdx.y * 32, l = blockIdx.z;
    int tx = threadIdx.x, ty = threadIdx.y;   // (32, 8)
    const float* src = ipw + (size_t)l * 331776;
    float* dst = g_wT + (size_t)l * 331776;
    #pragma unroll
    for (int i = 0; i < 4; i++)
        tile[ty + 8 * i][tx] = src[(size_t)(c0 + ty + 8 * i) * 864 + r0 + tx];
    __syncthreads();
    #pragma unroll
    for (int i = 0; i < 4; i++)
        dst[(size_t)(r0 + ty + 8 * i) * 384 + c0 + tx] = tile[tx][ty + 8 * i];
}

// ---------- GEMV weight interleave (one-time, tiny) ----------
__global__ void wgx_kernel(const float* __restrict__ xpw, const float* __restrict__ opw) {
    int l = blockIdx.x;
    int tid = threadIdx.x;
    const float* xs = xpw + (size_t)l * 38 * 192;
    float4* xd = g_xp2 + (size_t)l * 48 * 38;
    for (int i = tid; i < 48 * 38; i += 256) {
        int c4 = i / 38, j = i % 38;
        xd[i] = *(const float4*)(xs + (size_t)j * 192 + c4 * 4);
    }
    const float* os = opw + (size_t)l * 96 * 192;
    float4* od = g_op2 + (size_t)l * 48 * 96;
    for (int i = tid; i < 48 * 96; i += 256) {
        int c4 = i / 96, k = i % 96;
        od[i] = *(const float4*)(os + (size_t)k * 192 + c4 * 4);
    }
}

// ---------- rms row scales (no data rewrite) ----------
__global__ void rs_kernel(const float* __restrict__ src, long cs, long ns,
                          const float* __restrict__ nw, float* __restrict__ rs) {
    int row = blockIdx.x * 128 + threadIdx.x;
    if (row >= 2 * 96 * 24) return;
    int h = row % 24;
    int c = (row / 24) % 96;
    int n = row / (24 * 96);
    const float* p = src + (size_t)n * ns + (size_t)c * cs + h * 24;
    float s = 0.f;
    #pragma unroll
    for (int j = 0; j < 6; j++) {
        float4 v = *(const float4*)(p + 4 * j);
        s += v.x * v.x + v.y * v.y + v.z * v.z + v.w * v.w;
    }
    rs[(n * 96 + c) * 24 + h] = rsqrtf(s * (1.f / 24.f) + 1e-5f) * __ldg(nw + c);
}

// ---------- 3x3 conv (96 -> 384), scale at staging, weights via direct LDG (R10) ----------
__global__ void __launch_bounds__(192, 3)
conv_kernel(const float* __restrict__ wT,
            const float* __restrict__ src, long cs, long ns,
            const float* __restrict__ rs,
            float* __restrict__ outp) {
    extern __shared__ float sm[];
    float2* S2 = (float2*)sm;          // [144][28] float2, values duplicated

    int h0  = blockIdx.x * 4;
    int ct  = blockIdx.y;
    int n   = blockIdx.z >> 2;
    int kq  = blockIdx.z & 3;
    int ci0 = kq * 24;
    int tid = threadIdx.x;

    const float* sb = src + (size_t)n * ns + (size_t)ci0 * cs;
    const float* rb = rs + (n * 96 + ci0) * 24;
    for (int idx = tid; idx < 24 * 6 * 24; idx += 192) {
        int w = idx % 24;
        int row = idx / 24;
        int hr = row % 6, ci = row / 6;
        int hh = h0 + hr - 1;
        float v = 0.f;
        if (hh >= 0 && hh < 24)
            v = sb[(size_t)ci * cs + hh * 24 + w] * __ldg(rb + ci * 24 + hh);
        S2[row * 28 + 1 + w] = make_float2(v, v);
    }
    if (tid < 144) {
        float2 z = make_float2(0.f, 0.f);
        S2[tid * 28] = z; S2[tid * 28 + 25] = z;
        S2[tid * 28 + 26] = z; S2[tid * 28 + 27] = z;
    }
    __syncthreads();

    int cog  = tid & 15;
    int posg = tid >> 4;
    int hl   = (posg / 6) * 2;
    int w0   = (posg % 6) * 4;

    ull acc[2][2][4];
    #pragma unroll
    for (int a = 0; a < 2; a++)
        #pragma unroll
        for (int dh = 0; dh < 2; dh++)
            #pragma unroll
            for (int dw = 0; dw < 4; dw++) acc[a][dh][dw] = 0ull;

    const float2* Sbase = S2 + hl * 28 + w0;
    const float*  Wg = wT + (size_t)(ci0 * 9) * 384 + ct * 64 + cog * 4;

    #pragma unroll 1
    for (int ci = 0; ci < 24; ci++) {
        const float* Wr = Wg + (size_t)ci * 9 * 384;
        float4 wv[9];
        #pragma unroll
        for (int t = 0; t < 9; t++)
            wv[t] = __ldg((const float4*)(Wr + (size_t)t * 384));

        const float2* Sr = Sbase + ci * 168;
        ull ind[4][6];
        #pragma unroll
        for (int r = 0; r < 4; r++) {
            const float4* rp = (const float4*)(Sr + r * 28);
            float4 t0 = rp[0], t1 = rp[1], t2 = rp[2];
            ind[r][0] = *(ull*)&t0.x; ind[r][1] = *(ull*)&t0.z;
            ind[r][2] = *(ull*)&t1.x; ind[r][3] = *(ull*)&t1.z;
            ind[r][4] = *(ull*)&t2.x; ind[r][5] = *(ull*)&t2.z;
        }

        #pragma unroll
        for (int kh = 0; kh < 3; kh++) {
            #pragma unroll
            for (int kw = 0; kw < 3; kw++) {
                ull w01 = *(const ull*)&wv[kh * 3 + kw].x;
                ull w23 = *(const ull*)&wv[kh * 3 + kw].z;
                #pragma unroll
                for (int dh = 0; dh < 2; dh++) {
                    #pragma unroll
                    for (int dw = 0; dw < 4; dw++) {
                        ffma2(acc[0][dh][dw], w01, ind[dh + kh][dw + kw]);
                        ffma2(acc[1][dh][dw], w23, ind[dh + kh][dw + kw]);
                    }
                }
            }
        }
    }

    int cobase = ct * 64 + cog * 4;
    float* ob = outp + (size_t)kq * XZQ
              + ((size_t)(n * 384 + cobase)) * NPOS + (h0 + hl) * 24 + w0;
    #pragma unroll
    for (int a = 0; a < 2; a++) {
        #pragma unroll
        for (int dh = 0; dh < 2; dh++) {
            float2 v0 = up(acc[a][dh][0]), v1 = up(acc[a][dh][1]);
            float2 v2 = up(acc[a][dh][2]), v3 = up(acc[a][dh][3]);
            float4 lo = make_float4(v0.x, v1.x, v2.x, v3.x);
            float4 hi = make_float4(v0.y, v1.y, v2.y, v3.y);
            *(float4*)(ob + (size_t)(2 * a) * NPOS + dh * 24)     = lo;
            *(float4*)(ob + (size_t)(2 * a + 1) * NPOS + dh * 24) = hi;
        }
    }
}

// ---------- fused (R10 structure; ONLY weight layout changed to interleaved) ----------
// 384 threads (12 warps), grid (72 ptiles, 2 n).
__global__ void __launch_bounds__(384, 1)
fused_kernel(const float* __restrict__ cw,  const float* __restrict__ cb,
             const float4* __restrict__ xp2, const float* __restrict__ dtw,
             const float* __restrict__ dtb, const float* __restrict__ Dp,
             const float4* __restrict__ op2,
             const float* __restrict__ resid, long cs, long ns,
             float* __restrict__ dst) {
    __shared__ float xi_s[192 * 8];
    __shared__ float dbc_s[38 * 8];
    __shared__ float bc_s[8];

    int tid = threadIdx.x;
    int p0 = blockIdx.x * 8;
    int n  = blockIdx.y;
    const float* xzb = g_xz + (size_t)n * 384 * NPOS + p0;

    // phase 1: xi = silu(conv1d depth-0 tap + bias); sum four K-quarters
    for (int idx = tid; idx < 1536; idx += 384) {
        int c = idx >> 3, p = idx & 7;
        size_t o = (size_t)c * NPOS + p;
        float v = xzb[o] + xzb[XZQ + o] + xzb[2 * XZQ + o] + xzb[3 * XZQ + o];
        float pre = __ldg(cw + c * 4 + 3) * v + __ldg(cb + c);
        xi_s[idx] = pre / (1.f + __expf(-pre));
    }
    __syncthreads();

    // phase 2: dbc[38][8] = x_proj @ xi   (thread = (j, pos-pair); 1-line warp loads)
    {
        int j = tid >> 2, pp = tid & 3;
        if (j < 38) {
            float a0 = 0.f, b0 = 0.f, a1 = 0.f, b1 = 0.f;
            const float4* wr = xp2 + j;
            const float* xr = xi_s + pp * 2;
            #pragma unroll 6
            for (int c4 = 0; c4 < 24; c4++) {
                float4 w  = __ldg(wr + (size_t)c4 * 38);
                float4 w2 = __ldg(wr + (size_t)(c4 + 24) * 38);
                #pragma unroll
                for (int u = 0; u < 4; u++) {
                    float wv = (&w.x)[u];
                    float2 x = *(const float2*)(xr + (4 * c4 + u) * 8);
                    a0 += wv * x.x; b0 += wv * x.y;
                    float wv2 = (&w2.x)[u];
                    float2 x2 = *(const float2*)(xr + (96 + 4 * c4 + u) * 8);
                    a1 += wv2 * x2.x; b1 += wv2 * x2.y;
                }
            }
            dbc_s[j * 8 + pp * 2]     = a0 + a1;
            dbc_s[j * 8 + pp * 2 + 1] = b0 + b1;
        }
    }
    __syncthreads();

    // phase 3: bc[p] = B . C
    if (tid < 8) {
        float s = 0.f;
        #pragma unroll
        for (int qq = 0; qq < 16; qq++)
            s += dbc_s[(6 + qq) * 8 + tid] * dbc_s[(22 + qq) * 8 + tid];
        bc_s[tid] = s;
    }
    __syncthreads();

    // phase 4: delta -> y -> gate; overwrite xi_s with g (thread = channel)
    if (tid < 192) {
        int c = tid;
        float dw[6];
        #pragma unroll
        for (int r = 0; r < 6; r++) dw[r] = __ldg(dtw + c * 6 + r);
        float bconst = __ldg(dtb + c);
        float Dc = __ldg(Dp + c);
        const float* zrow = xzb + (size_t)(192 + c) * NPOS;
        float z[8];
        #pragma unroll
        for (int jj = 0; jj < 2; jj++) {
            float4 a = *(const float4*)(zrow + 4 * jj);
            #pragma unroll
            for (int q = 1; q < 4; q++) {
                float4 t = *(const float4*)(zrow + (size_t)q * XZQ + 4 * jj);
                a.x += t.x; a.y += t.y; a.z += t.z; a.w += t.w;
            }
            z[4 * jj] = a.x; z[4 * jj + 1] = a.y; z[4 * jj + 2] = a.z; z[4 * jj + 3] = a.w;
        }
        #pragma unroll
        for (int p = 0; p < 8; p++) {
            float d = bconst;
            #pragma unroll
            for (int r = 0; r < 6; r++) d += dw[r] * dbc_s[r * 8 + p];
            float sp = fmaxf(d, 0.f) + log1pf(__expf(-fabsf(d)));
            float zv = z[p];
            xi_s[c * 8 + p] = xi_s[c * 8 + p] * (sp * bc_s[p] + Dc)
                            * (zv / (1.f + __expf(-zv)));
        }
    }
    __syncthreads();

    // phase 5: out = out_proj @ g + residual (thread = (k, pos-pair); 1-line warp loads)
    {
        int k = tid >> 2, pp = tid & 3;
        float a0 = 0.f, b0 = 0.f, a1 = 0.f, b1 = 0.f;
        const float4* wr = op2 + k;
        const float* xr = xi_s + pp * 2;
        #pragma unroll 6
        for (int c4 = 0; c4 < 24; c4++) {
            float4 w  = __ldg(wr + (size_t)c4 * 96);
            float4 w2 = __ldg(wr + (size_t)(c4 + 24) * 96);
            #pragma unroll
            for (int u = 0; u < 4; u++) {
                float wv = (&w.x)[u];
                float2 x = *(const float2*)(xr + (4 * c4 + u) * 8);
                a0 += wv * x.x; b0 += wv * x.y;
                float wv2 = (&w2.x)[u];
                float2 x2 = *(const float2*)(xr + (96 + 4 * c4 + u) * 8);
                a1 += wv2 * x2.x; b1 += wv2 * x2.y;
            }
        }
        const float* rb = resid + (size_t)n * ns + (size_t)k * cs + p0 + pp * 2;
        float2 v = make_float2(a0 + a1 + rb[0], b0 + b1 + rb[1]);
        *(float2*)(dst + (size_t)(n * 96 + k) * NPOS + p0 + pp * 2) = v;
    }
}

extern "C" void kernel_launch(void* const* d_in, const int* in_sizes, int n_in,
                              void* d_out, int out_size) {
    const float* x          = (const float*)d_in[0];
    const float* in_proj_w  = (const float*)d_in[1];
    const float* conv1d_w   = (const float*)d_in[2];
    const float* conv1d_b   = (const float*)d_in[3];
    const float* x_proj_w   = (const float*)d_in[4];
    const float* dt_proj_w  = (const float*)d_in[5];
    const float* dt_proj_b  = (const float*)d_in[6];
    // d_in[7] = A_log : unused (hs at depth 0 == BX at depth 0)
    const float* Dp         = (const float*)d_in[8];
    const float* out_proj_w = (const float*)d_in[9];
    const float* norm_w     = (const float*)d_in[10];
    float* out = (float*)d_out;

    float *xz = nullptr, *mid = nullptr, *wT = nullptr, *rs0 = nullptr, *rs1 = nullptr;
    float4 *xp2 = nullptr, *op2 = nullptr;
    cudaGetSymbolAddress((void**)&xz, g_xz);
    cudaGetSymbolAddress((void**)&mid, g_mid);
    cudaGetSymbolAddress((void**)&wT, g_wT);
    cudaGetSymbolAddress((void**)&rs0, g_rs0);
    cudaGetSymbolAddress((void**)&rs1, g_rs1);
    cudaGetSymbolAddress((void**)&xp2, g_xp2);
    cudaGetSymbolAddress((void**)&op2, g_op2);

    const int CONV_SMEM = 144 * 56 * 4;   // 32256
    cudaFuncSetAttribute(conv_kernel, cudaFuncAttributeMaxDynamicSharedMemorySize, CONV_SMEM);

    wt_kernel<<<dim3(27, 12, 2), dim3(32, 8)>>>(in_proj_w);
    wgx_kernel<<<2, 256>>>(x_proj_w, out_proj_w);

    // layer 0: input = x depth-0 slice (strided view)
    {
        long cs = 8L * NPOS, ns = 96L * 8L * NPOS;
        rs_kernel<<<36, 128>>>(x, cs, ns, norm_w, rs0);
        conv_kernel<<<dim3(6, 6, 8), 192, CONV_SMEM>>>(wT, x, cs, ns, rs0, xz);
        fused_kernel<<<dim3(72, 2), 384>>>(
            conv1d_w, conv1d_b, xp2, dt_proj_w, dt_proj_b, Dp, op2,
            x, cs, ns, mid);
    }
    // layer 1: input = mid (contiguous)
    {
        long cs = (long)NPOS, ns = 96L * NPOS;
        rs_kernel<<<36, 128>>>(mid, cs, ns, norm_w + 96, rs1);
        conv_kernel<<<dim3(6, 6, 8), 192, CONV_SMEM>>>(
            wT + 331776, mid, cs, ns, rs1, xz);
        fused_kernel<<<dim3(72, 2), 384>>>(
            conv1d_w + 768, conv1d_b + 192, xp2 + 48 * 38, dt_proj_w + 1152,
            dt_proj_b + 192, Dp + 192, op2 + 48 * 96,
            mid, cs, ns, out);
    }
}

// round 14
// speedup vs baseline: 1.0477x; 1.0477x over previous
#include <cuda_runtime.h>
#include <math.h>

#define HW 24
#define NPOS 576
#define XZH 442368            // one K-half of xz: 2n * 384 * 576

// Scratch (__device__ globals: allocation-free rule)
__device__ float g_xz[2 * XZH];          // [khalf][n][384][576]
__device__ float g_mid[2 * 96 * NPOS];
__device__ float g_wT[2 * 864 * 384];
__device__ float g_rs0[2 * 96 * 24];     // layer-0 rms row scales
__device__ float g_rs1[2 * 96 * 24];     // layer-1 rms row scales

typedef unsigned long long ull;

__device__ __forceinline__ void ffma2(ull& acc, ull a, ull b) {
    asm("fma.rn.f32x2 %0, %1, %2, %0;" : "+l"(acc) : "l"(a), "l"(b));
}
__device__ __forceinline__ float2 up(ull a) { return *(float2*)&a; }

// ---------- weight transpose: [co][ci*9+t] -> [ci*9+t][co] ----------
__global__ void wt_kernel(const float* __restrict__ ipw) {
    __shared__ float tile[32][33];
    int r0 = blockIdx.x * 32, c0 = blockIdx.y * 32, l = blockIdx.z;
    int tx = threadIdx.x, ty = threadIdx.y;   // (32, 8)
    const float* src = ipw + (size_t)l * 331776;
    float* dst = g_wT + (size_t)l * 331776;
    #pragma unroll
    for (int i = 0; i < 4; i++)
        tile[ty + 8 * i][tx] = src[(size_t)(c0 + ty + 8 * i) * 864 + r0 + tx];
    __syncthreads();
    #pragma unroll
    for (int i = 0; i < 4; i++)
        dst[(size_t)(r0 + ty + 8 * i) * 384 + c0 + tx] = tile[tx][ty + 8 * i];
}

// ---------- rms row scales (no data rewrite) ----------
__global__ void rs_kernel(const float* __restrict__ src, long cs, long ns,
                          const float* __restrict__ nw, float* __restrict__ rs) {
    int row = blockIdx.x * 128 + threadIdx.x;
    if (row >= 2 * 96 * 24) return;
    int h = row % 24;
    int c = (row / 24) % 96;
    int n = row / (24 * 96);
    const float* p = src + (size_t)n * ns + (size_t)c * cs + h * 24;
    float s = 0.f;
    #pragma unroll
    for (int j = 0; j < 6; j++) {
        float4 v = *(const float4*)(p + 4 * j);
        s += v.x * v.x + v.y * v.y + v.z * v.z + v.w * v.w;
    }
    rs[(n * 96 + c) * 24 + h] = rsqrtf(s * (1.f / 24.f) + 1e-5f) * __ldg(nw + c);
}

// ---------- 3x3 conv (96 -> 384), scale at staging, K-split by 2 ----------
// block: 64 co x (2h x 24w), 48-ci half; 192 threads
// grid: (12 htile, 6 ctile, 4 = n*2 + ks)
// thread tile: 4 co (2 f32x2 co-pairs) x 1 h x 4 w
__global__ void __launch_bounds__(192, 3)
conv_kernel(const float* __restrict__ wT,
            const float* __restrict__ src, long cs, long ns,
            const float* __restrict__ rs,
            float* __restrict__ outp) {
    extern __shared__ float sm[];
    float2* S2 = (float2*)sm;          // [48ci][4rows][28] float2, duplicated

    int h0  = blockIdx.x * 2;
    int ct  = blockIdx.y;
    int n   = blockIdx.z >> 1;
    int ks  = blockIdx.z & 1;
    int ci0 = ks * 48;
    int tid = threadIdx.x;

    // stage normalized input (48 ci, 4 h rows with halo), duplicated float2
    const float* sb = src + (size_t)n * ns + (size_t)ci0 * cs;
    const float* rb = rs + (n * 96 + ci0) * 24;
    for (int idx = tid; idx < 48 * 4 * 24; idx += 192) {
        int w = idx % 24;
        int row = idx / 24;            // ci*4 + hr
        int hr = row & 3, ci = row >> 2;
        int hh = h0 + hr - 1;
        float v = 0.f;
        if (hh >= 0 && hh < 24)
            v = sb[(size_t)ci * cs + hh * 24 + w] * __ldg(rb + ci * 24 + hh);
        S2[row * 28 + 1 + w] = make_float2(v, v);
    }
    {   // 192 rows total, one per thread: zero the pads
        float2 z = make_float2(0.f, 0.f);
        S2[tid * 28] = z; S2[tid * 28 + 25] = z;
        S2[tid * 28 + 26] = z; S2[tid * 28 + 27] = z;
    }
    __syncthreads();

    int cog  = tid & 15;               // co_local = cog*4
    int posg = tid >> 4;               // 0..11
    int hl   = posg / 6;               // 0 or 1
    int w0   = (posg % 6) * 4;         // 0,4,...,20 (f2 units, 16B-aligned)

    ull acc[2][4];
    #pragma unroll
    for (int a = 0; a < 2; a++)
        #pragma unroll
        for (int dw = 0; dw < 4; dw++) acc[a][dw] = 0ull;

    const float2* Sbase = S2 + hl * 28 + w0;
    const float*  Wg = wT + (size_t)(ci0 * 9) * 384 + ct * 64 + cog * 4;

    #pragma unroll 1
    for (int ci = 0; ci < 48; ci++) {
        const float* Wr = Wg + (size_t)ci * 9 * 384;
        float4 wv[9];
        #pragma unroll
        for (int t = 0; t < 9; t++)
            wv[t] = __ldg((const float4*)(Wr + (size_t)t * 384));

        const float2* Sr = Sbase + ci * 112;   // ci*4 rows * 28
        ull R[3][6];
        #pragma unroll
        for (int r = 0; r < 3; r++) {
            const float4* rp = (const float4*)(Sr + r * 28);
            float4 t0 = rp[0], t1 = rp[1], t2 = rp[2];
            R[r][0] = *(ull*)&t0.x; R[r][1] = *(ull*)&t0.z;
            R[r][2] = *(ull*)&t1.x; R[r][3] = *(ull*)&t1.z;
            R[r][4] = *(ull*)&t2.x; R[r][5] = *(ull*)&t2.z;
        }

        #pragma unroll
        for (int kh = 0; kh < 3; kh++) {
            #pragma unroll
            for (int kw = 0; kw < 3; kw++) {
                ull w01 = *(const ull*)&wv[kh * 3 + kw].x;
                ull w23 = *(const ull*)&wv[kh * 3 + kw].z;
                #pragma unroll
                for (int dw = 0; dw < 4; dw++) {
                    ffma2(acc[0][dw], w01, R[kh][dw + kw]);
                    ffma2(acc[1][dw], w23, R[kh][dw + kw]);
                }
            }
        }
    }

    int cobase = ct * 64 + cog * 4;
    float* ob = outp + (size_t)ks * XZH
              + ((size_t)(n * 384 + cobase)) * NPOS + (h0 + hl) * 24 + w0;
    #pragma unroll
    for (int a = 0; a < 2; a++) {
        float2 v0 = up(acc[a][0]), v1 = up(acc[a][1]);
        float2 v2 = up(acc[a][2]), v3 = up(acc[a][3]);
        float4 lo = make_float4(v0.x, v1.x, v2.x, v3.x);
        float4 hi = make_float4(v0.y, v1.y, v2.y, v3.y);
        *(float4*)(ob + (size_t)(2 * a) * NPOS)     = lo;
        *(float4*)(ob + (size_t)(2 * a + 1) * NPOS) = hi;
    }
}

// ---------- fused pointwise chain + GEMVs over 8-position tiles (R10 structure) ----------
// 384 threads (12 warps), grid (72 ptiles, 2 n). Sums TWO K-halves.
__global__ void __launch_bounds__(384, 1)
fused_kernel(const float* __restrict__ cw,  const float* __restrict__ cb,
             const float* __restrict__ xpw, const float* __restrict__ dtw,
             const float* __restrict__ dtb, const float* __restrict__ Dp,
             const float* __restrict__ opw,
             const float* __restrict__ resid, long cs, long ns,
             float* __restrict__ dst) {
    __shared__ float xi_s[192 * 8];
    __shared__ float dbc_s[38 * 8];
    __shared__ float bc_s[8];

    int tid = threadIdx.x;
    int p0 = blockIdx.x * 8;
    int n  = blockIdx.y;
    const float* xzb = g_xz + (size_t)n * 384 * NPOS + p0;

    // phase 1: xi = silu(conv1d depth-0 tap + bias); sum two K-halves
    for (int idx = tid; idx < 1536; idx += 384) {
        int c = idx >> 3, p = idx & 7;
        size_t o = (size_t)c * NPOS + p;
        float v = xzb[o] + xzb[XZH + o];
        float pre = __ldg(cw + c * 4 + 3) * v + __ldg(cb + c);
        xi_s[idx] = pre / (1.f + __expf(-pre));
    }
    __syncthreads();

    // phase 2: dbc[38][8] = x_proj @ xi   (thread = (j, pos-pair))
    {
        int j = tid >> 2, pp = tid & 3;
        if (j < 38) {
            float a0 = 0.f, b0 = 0.f, a1 = 0.f, b1 = 0.f;
            const float4* wr = (const float4*)(xpw + (size_t)j * 192);
            const float* xr = xi_s + pp * 2;
            #pragma unroll 6
            for (int c4 = 0; c4 < 24; c4++) {
                float4 w = __ldg(wr + c4);
                float4 w2 = __ldg(wr + 24 + c4);
                #pragma unroll
                for (int u = 0; u < 4; u++) {
                    float wv = (&w.x)[u];
                    float2 x = *(const float2*)(xr + (4 * c4 + u) * 8);
                    a0 += wv * x.x; b0 += wv * x.y;
                    float wv2 = (&w2.x)[u];
                    float2 x2 = *(const float2*)(xr + (96 + 4 * c4 + u) * 8);
                    a1 += wv2 * x2.x; b1 += wv2 * x2.y;
                }
            }
            dbc_s[j * 8 + pp * 2]     = a0 + a1;
            dbc_s[j * 8 + pp * 2 + 1] = b0 + b1;
        }
    }
    __syncthreads();

    // phase 3: bc[p] = B . C
    if (tid < 8) {
        float s = 0.f;
        #pragma unroll
        for (int qq = 0; qq < 16; qq++)
            s += dbc_s[(6 + qq) * 8 + tid] * dbc_s[(22 + qq) * 8 + tid];
        bc_s[tid] = s;
    }
    __syncthreads();

    // phase 4: delta -> y -> gate; overwrite xi_s with g (thread = channel)
    if (tid < 192) {
        int c = tid;
        float dw[6];
        #pragma unroll
        for (int r = 0; r < 6; r++) dw[r] = __ldg(dtw + c * 6 + r);
        float bconst = __ldg(dtb + c);
        float Dc = __ldg(Dp + c);
        const float* zrow = xzb + (size_t)(192 + c) * NPOS;
        float z[8];
        #pragma unroll
        for (int jj = 0; jj < 2; jj++) {
            float4 a = *(const float4*)(zrow + 4 * jj);
            float4 t = *(const float4*)(zrow + XZH + 4 * jj);
            a.x += t.x; a.y += t.y; a.z += t.z; a.w += t.w;
            z[4 * jj] = a.x; z[4 * jj + 1] = a.y; z[4 * jj + 2] = a.z; z[4 * jj + 3] = a.w;
        }
        #pragma unroll
        for (int p = 0; p < 8; p++) {
            float d = bconst;
            #pragma unroll
            for (int r = 0; r < 6; r++) d += dw[r] * dbc_s[r * 8 + p];
            float sp = fmaxf(d, 0.f) + log1pf(__expf(-fabsf(d)));
            float zv = z[p];
            xi_s[c * 8 + p] = xi_s[c * 8 + p] * (sp * bc_s[p] + Dc)
                            * (zv / (1.f + __expf(-zv)));
        }
    }
    __syncthreads();

    // phase 5: out = out_proj @ g + residual (thread = (k, pos-pair), 96x4 = 384)
    {
        int k = tid >> 2, pp = tid & 3;
        float a0 = 0.f, b0 = 0.f, a1 = 0.f, b1 = 0.f;
        const float4* wr = (const float4*)(opw + (size_t)k * 192);
        const float* xr = xi_s + pp * 2;
        #pragma unroll 6
        for (int c4 = 0; c4 < 24; c4++) {
            float4 w = __ldg(wr + c4);
            float4 w2 = __ldg(wr + 24 + c4);
            #pragma unroll
            for (int u = 0; u < 4; u++) {
                float wv = (&w.x)[u];
                float2 x = *(const float2*)(xr + (4 * c4 + u) * 8);
                a0 += wv * x.x; b0 += wv * x.y;
                float wv2 = (&w2.x)[u];
                float2 x2 = *(const float2*)(xr + (96 + 4 * c4 + u) * 8);
                a1 += wv2 * x2.x; b1 += wv2 * x2.y;
            }
        }
        const float* rb = resid + (size_t)n * ns + (size_t)k * cs + p0 + pp * 2;
        float2 v = make_float2(a0 + a1 + rb[0], b0 + b1 + rb[1]);
        *(float2*)(dst + (size_t)(n * 96 + k) * NPOS + p0 + pp * 2) = v;
    }
}

extern "C" void kernel_launch(void* const* d_in, const int* in_sizes, int n_in,
                              void* d_out, int out_size) {
    const float* x          = (const float*)d_in[0];
    const float* in_proj_w  = (const float*)d_in[1];
    const float* conv1d_w   = (const float*)d_in[2];
    const float* conv1d_b   = (const float*)d_in[3];
    const float* x_proj_w   = (const float*)d_in[4];
    const float* dt_proj_w  = (const float*)d_in[5];
    const float* dt_proj_b  = (const float*)d_in[6];
    // d_in[7] = A_log : unused (hs at depth 0 == BX at depth 0)
    const float* Dp         = (const float*)d_in[8];
    const float* out_proj_w = (const float*)d_in[9];
    const float* norm_w     = (const float*)d_in[10];
    float* out = (float*)d_out;

    float *xz = nullptr, *mid = nullptr, *wT = nullptr, *rs0 = nullptr, *rs1 = nullptr;
    cudaGetSymbolAddress((void**)&xz, g_xz);
    cudaGetSymbolAddress((void**)&mid, g_mid);
    cudaGetSymbolAddress((void**)&wT, g_wT);
    cudaGetSymbolAddress((void**)&rs0, g_rs0);
    cudaGetSymbolAddress((void**)&rs1, g_rs1);

    const int CONV_SMEM = 192 * 28 * 8;   // 43008
    cudaFuncSetAttribute(conv_kernel, cudaFuncAttributeMaxDynamicSharedMemorySize, CONV_SMEM);

    wt_kernel<<<dim3(27, 12, 2), dim3(32, 8)>>>(in_proj_w);

    // layer 0: input = x depth-0 slice (strided view)
    {
        long cs = 8L * NPOS, ns = 96L * 8L * NPOS;
        rs_kernel<<<36, 128>>>(x, cs, ns, norm_w, rs0);
        conv_kernel<<<dim3(12, 6, 4), 192, CONV_SMEM>>>(wT, x, cs, ns, rs0, xz);
        fused_kernel<<<dim3(72, 2), 384>>>(
            conv1d_w, conv1d_b, x_proj_w, dt_proj_w, dt_proj_b, Dp, out_proj_w,
            x, cs, ns, mid);
    }
    // layer 1: input = mid (contiguous)
    {
        long cs = (long)NPOS, ns = 96L * NPOS;
        rs_kernel<<<36, 128>>>(mid, cs, ns, norm_w + 96, rs1);
        conv_kernel<<<dim3(12, 6, 4), 192, CONV_SMEM>>>(
            wT + 331776, mid, cs, ns, rs1, xz);
        fused_kernel<<<dim3(72, 2), 384>>>(
            conv1d_w + 768, conv1d_b + 192, x_proj_w + 7296, dt_proj_w + 1152,
            dt_proj_b + 192, Dp + 192, out_proj_w + 18432,
            mid, cs, ns, out);
    }
}